// round 14
// baseline (speedup 1.0000x reference)
#include <cuda_runtime.h>
#include <cuda_fp16.h>
#include <cstdint>

// ---------------------------------------------------------------------------
// LatentLayer loss via warp-level mma.sync (HMMA) + f16x2 MUFU (R13):
//   C^T[m,k] = sum_i H[m,i] * G[i,k]   (1024 x 16 x 8192, f16 in, f32 accum)
//   H[m,i] = exp2(sZx_i*tex_m + sZy_i*tey_m),  sZ = L2E*u*z, te = T*eps
//   G[i,k] = exp2(a2_i + sZx_i*mx_k + sZy_i*my_k), a2 = L2E*alpha*|z|^2
//   lse_j = alpha*|e_j|^2 + ln(C),  loss = -mean(lse) + (2ls-1) + ln(N)
// Exponentials computed with ex2.approx.f16x2 on packed fp16 pairs (the MMA
// operands are fp16 anyway) -> MUFU instruction count halved vs R11.
// Grid: 512 CTAs = 8 m-tiles(128 m) x 64 K-slices(128 i), 256 threads.
// Warp w owns m-rows [128*mt + 16*w, +16) x all 16 emb over its 128-i slice:
// 8 k-steps, 2 x mma.m16n8k16 per step, A fragments computed IN REGISTERS.
// Epilogue: 4 x red.global.add.v2.f32 per thread into g_Ct (64 contrib/addr).
// Last-arriving CTA computes the lse reduction and resets state for replay.
// ---------------------------------------------------------------------------

#define N_Z      8192
#define M_EPS    1024
#define N_EMB    16
#define GRID     512
#define NTHR     256
#define ISLICE   128               // i per CTA
#define M_TOT    (N_EMB * M_EPS)   // 16384

__device__ __align__(16) float g_Ct[M_TOT];  // Ct[m][k], zero-init .bss
__device__ unsigned int g_done = 0;

__device__ __forceinline__ float lg2f(float x) {
    float y; asm("lg2.approx.ftz.f32 %0, %1;" : "=f"(y) : "f"(x)); return y;
}
// pack (lo, hi) f32 -> f16x2 register (lo in low half)
__device__ __forceinline__ uint32_t cvt_f16x2(float lo, float hi) {
    uint32_t r;
    asm("cvt.rn.satfinite.f16x2.f32 %0, %1, %2;" : "=r"(r) : "f"(hi), "f"(lo));
    return r;
}
// elementwise 2^x on a packed f16x2
__device__ __forceinline__ uint32_t ex2h2(uint32_t v) {
    uint32_t r;
    asm("ex2.approx.f16x2 %0, %1;" : "=r"(r) : "r"(v));
    return r;
}
// D = A(16x16,row) * B(16x8,col) + C, f16 inputs, f32 accum
__device__ __forceinline__ void mma16816(float* d, const uint32_t* a,
                                         uint32_t b0, uint32_t b1) {
    asm volatile(
        "mma.sync.aligned.m16n8k16.row.col.f32.f16.f16.f32 "
        "{%0,%1,%2,%3}, {%4,%5,%6,%7}, {%8,%9}, {%0,%1,%2,%3};"
        : "+f"(d[0]), "+f"(d[1]), "+f"(d[2]), "+f"(d[3])
        : "r"(a[0]), "r"(a[1]), "r"(a[2]), "r"(a[3]), "r"(b0), "r"(b1));
}

__global__ __launch_bounds__(NTHR, 4)
void fused_kernel(const float* __restrict__ z,
                  const float* __restrict__ emb,
                  const float* __restrict__ lsig,
                  const float* __restrict__ eps,
                  const float* __restrict__ temp,
                  float* __restrict__ out)
{
    __shared__ __align__(16) float2 sZ[ISLICE];              // (L2E*u*zx, L2E*u*zy)
    __shared__ __align__(16) float  sA2[ISLICE];             // L2E*alpha*|z|^2
    __shared__ __align__(16) __half sGt[N_EMB][ISLICE];      // G^T: [emb][i]
    __shared__ __align__(16) float4 sred[NTHR];              // tail only
    __shared__ int sIsLast;

    const int tid = threadIdx.x;
    const int wid = tid >> 5;
    const int lid = tid & 31;
    const int gid = lid >> 2;          // 0..7
    const int tig = lid & 3;           // 0..3
    const int mt  = blockIdx.x & 7;    // m-tile: m0 = mt*128
    const int ks  = blockIdx.x >> 3;   // K-slice: i0 = ks*128

    const float T   = temp[0];
    const float ls  = lsig[0];
    const float u   = __expf(-2.0f * ls);   // 1/sigma^2
    const float alpha = -0.5f * u;
    const float L2E = 1.4426950408889634f;
    const float LN2 = 0.6931471805599453f;

    // --- prologue 1: scaled z slice into smem ---
    if (tid < ISLICE) {
        float2 zz = reinterpret_cast<const float2*>(z)[ks * ISLICE + tid];
        sZ[tid]  = make_float2(L2E * u * zz.x, L2E * u * zz.y);
        sA2[tid] = L2E * alpha * (zz.x * zz.x + zz.y * zz.y);
    }
    __syncthreads();

    // --- prologue 2: G^T[16][128] fp16 in smem (8 values per thread) ---
    {
        const int k  = tid & 15;
        const int i8 = (tid >> 4) * 8;
        const float mx = (1.0f - T) * emb[2 * k];
        const float my = (1.0f - T) * emb[2 * k + 1];
        uint32_t* dst = (uint32_t*)&sGt[k][i8];
#pragma unroll
        for (int ii = 0; ii < 8; ii += 2) {
            float2 z0 = sZ[i8 + ii], z1 = sZ[i8 + ii + 1];
            float g0 = sA2[i8 + ii]     + fmaf(z0.x, mx, z0.y * my);
            float g1 = sA2[i8 + ii + 1] + fmaf(z1.x, mx, z1.y * my);
            dst[ii >> 1] = ex2h2(cvt_f16x2(g0, g1));
        }
    }

    // --- this thread's two m rows (fragment rows gid, gid+8) ---
    const int m0g = mt * 128 + wid * 16 + gid;
    const int m1g = m0g + 8;
    const float2 e0 = reinterpret_cast<const float2*>(eps)[m0g];
    const float2 e1 = reinterpret_cast<const float2*>(eps)[m1g];
    const float tex0 = T * e0.x, tey0 = T * e0.y;
    const float tex1 = T * e1.x, tey1 = T * e1.y;

    __syncthreads();

    float acc[8];
#pragma unroll
    for (int q = 0; q < 8; q++) acc[q] = 0.0f;

    // --- main loop: 8 k-steps of 16 i; A frags via f16x2 ex2, in registers ---
#pragma unroll
    for (int step = 0; step < 8; step++) {
        const int iA = step * 16 + tig * 2;   // i: iA, iA+1, iA+8, iA+9
        // one LDS.128 per pair: (zx0,zy0,zx1,zy1)
        float4 zp0 = *reinterpret_cast<const float4*>(&sZ[iA]);
        float4 zp1 = *reinterpret_cast<const float4*>(&sZ[iA + 8]);

        float b00 = fmaf(zp0.x, tex0, zp0.y * tey0);
        float b01 = fmaf(zp0.z, tex0, zp0.w * tey0);
        float b02 = fmaf(zp1.x, tex0, zp1.y * tey0);
        float b03 = fmaf(zp1.z, tex0, zp1.w * tey0);
        float b10 = fmaf(zp0.x, tex1, zp0.y * tey1);
        float b11 = fmaf(zp0.z, tex1, zp0.w * tey1);
        float b12 = fmaf(zp1.x, tex1, zp1.y * tey1);
        float b13 = fmaf(zp1.z, tex1, zp1.w * tey1);

        uint32_t a[4];
        a[0] = ex2h2(cvt_f16x2(b00, b01));   // A[gid  ][iA..iA+1]
        a[1] = ex2h2(cvt_f16x2(b10, b11));   // A[gid+8][iA..iA+1]
        a[2] = ex2h2(cvt_f16x2(b02, b03));   // A[gid  ][iA+8..iA+9]
        a[3] = ex2h2(cvt_f16x2(b12, b13));   // A[gid+8][iA+8..iA+9]

        // B frags: b0 = G[iA..iA+1][n], b1 = G[iA+8..iA+9][n]
        uint32_t b0 = *(const uint32_t*)&sGt[gid][iA];
        uint32_t b1 = *(const uint32_t*)&sGt[gid][iA + 8];
        uint32_t b2 = *(const uint32_t*)&sGt[gid + 8][iA];
        uint32_t b3 = *(const uint32_t*)&sGt[gid + 8][iA + 8];

        mma16816(acc,     a, b0, b1);   // n = 0..7   (emb k = gid)
        mma16816(acc + 4, a, b2, b3);   // n = 8..15  (emb k = gid+8)
    }

    // --- epilogue: red.v2 into g_Ct[m][k]; C frag rows m0g/m1g, cols tig*2 ---
    asm volatile("red.global.add.v2.f32 [%0], {%1, %2};"
                 :: "l"(&g_Ct[m0g * N_EMB + tig * 2]), "f"(acc[0]), "f"(acc[1])
                 : "memory");
    asm volatile("red.global.add.v2.f32 [%0], {%1, %2};"
                 :: "l"(&g_Ct[m1g * N_EMB + tig * 2]), "f"(acc[2]), "f"(acc[3])
                 : "memory");
    asm volatile("red.global.add.v2.f32 [%0], {%1, %2};"
                 :: "l"(&g_Ct[m0g * N_EMB + 8 + tig * 2]), "f"(acc[4]), "f"(acc[5])
                 : "memory");
    asm volatile("red.global.add.v2.f32 [%0], {%1, %2};"
                 :: "l"(&g_Ct[m1g * N_EMB + 8 + tig * 2]), "f"(acc[6]), "f"(acc[7])
                 : "memory");
    __threadfence();

    if (tid == 0) {
        unsigned int ticket = atomicAdd(&g_done, 1u);
        sIsLast = (ticket == GRID - 1);
    }
    __syncthreads();
    if (!sIsLast) return;

    // ===== last CTA: tail =====
    __threadfence();   // acquire: observe all red results

    float lgsum = 0.0f;
#pragma unroll
    for (int q2 = 0; q2 < M_TOT / (4 * NTHR); q2++) {   // 16 iters
        int j4 = q2 * NTHR + tid;
        float4 cc = reinterpret_cast<float4*>(g_Ct)[j4];
        reinterpret_cast<float4*>(g_Ct)[j4] = make_float4(0.f, 0.f, 0.f, 0.f);
        lgsum += lg2f(cc.x) + lg2f(cc.y) + lg2f(cc.z) + lg2f(cc.w);
    }
    // closed-form Sum_j |e_j|^2:
    //   = 1024*Sum_k|mk|^2 + 2T*(Sum_k mk)·(Sum_m em) + 16*T^2*Sum_m|em|^2
    float sx = 0.f, sy = 0.f, ss = 0.f;
#pragma unroll
    for (int q2 = 0; q2 < M_EPS / NTHR; q2++) {         // 4 iters
        int mm = q2 * NTHR + tid;
        float2 e = reinterpret_cast<const float2*>(eps)[mm];
        sx += e.x; sy += e.y; ss += e.x * e.x + e.y * e.y;
    }
    sred[tid] = make_float4(lgsum, sx, sy, ss);
    __syncthreads();
#pragma unroll
    for (int s = NTHR / 2; s > 0; s >>= 1) {
        if (tid < s) {
            float4 a = sred[tid], b = sred[tid + s];
            sred[tid] = make_float4(a.x + b.x, a.y + b.y, a.z + b.z, a.w + b.w);
        }
        __syncthreads();
    }
    if (tid == 0) {
        float4 r = sred[0];
        float mkx = 0.f, mky = 0.f, mk2 = 0.f;
        for (int k = 0; k < N_EMB; k++) {
            float mxk = (1.0f - T) * emb[2 * k];
            float myk = (1.0f - T) * emb[2 * k + 1];
            mkx += mxk; mky += myk; mk2 += mxk * mxk + myk * myk;
        }
        float Se = (float)M_EPS * mk2
                 + 2.0f * T * (mkx * r.y + mky * r.z)
                 + (float)N_EMB * T * T * r.w;
        float sum_lse = alpha * Se + LN2 * r.x;
        g_done = 0;       // reset counter for next replay
        out[0] = -sum_lse / (float)M_TOT + (2.0f * ls - 1.0f) + logf((float)N_Z);
    }
}

// ---------------------------------------------------------------------------
extern "C" void kernel_launch(void* const* d_in, const int* in_sizes, int n_in,
                              void* d_out, int out_size)
{
    const float* z    = (const float*)d_in[0];
    const float* emb  = (const float*)d_in[1];
    const float* lsig = (const float*)d_in[2];
    const float* eps  = (const float*)d_in[3];
    const float* temp = (const float*)d_in[4];
    float* out = (float*)d_out;

    fused_kernel<<<GRID, NTHR>>>(z, emb, lsig, eps, temp, out);
}

// round 17
// speedup vs baseline: 1.1015x; 1.1015x over previous
#include <cuda_runtime.h>
#include <cuda_fp16.h>
#include <cstdint>

// ---------------------------------------------------------------------------
// LatentLayer loss via warp-level mma.sync (HMMA), two graph nodes (R14):
//   C^T[m,k] = sum_i H[m,i] * G[i,k]   (1024 x 16 x 8192, f16 in, f32 accum)
//   H[m,i] = exp2(sZx_i*tex_m + sZy_i*tey_m),  sZ = L2E*u*z, te = T*eps
//   G[i,k] = exp2(a2_i + sZx_i*mx_k + sZy_i*my_k), a2 = L2E*alpha*|z|^2
//   lse_j = alpha*|e_j|^2 + ln(C),  loss = -mean(lse) + (2ls-1) + ln(N)
// Node 1 (512 CTAs x 256): GEMM partials + red.global.add.v2 into g_Ct.
//   No fence / ticket / spin -- the kernel boundary orders the reds.
// Node 2 (1 x 512): lg2-sum over g_Ct (zeroing it for the next replay),
//   closed-form Sum|e|^2, final loss.
// ---------------------------------------------------------------------------

#define N_Z      8192
#define M_EPS    1024
#define N_EMB    16
#define GRID     512
#define NTHR     256
#define TAILTHR  512
#define ISLICE   128               // i per CTA
#define M_TOT    (N_EMB * M_EPS)   // 16384

__device__ __align__(16) float g_Ct[M_TOT];  // Ct[m][k], zero-init .bss

__device__ __forceinline__ float ex2f(float x) {
    float y; asm("ex2.approx.ftz.f32 %0, %1;" : "=f"(y) : "f"(x)); return y;
}
__device__ __forceinline__ float lg2f(float x) {
    float y; asm("lg2.approx.ftz.f32 %0, %1;" : "=f"(y) : "f"(x)); return y;
}
// pack (lo, hi) f32 -> f16x2 register (lo in low half)
__device__ __forceinline__ uint32_t cvt_f16x2(float lo, float hi) {
    uint32_t r;
    asm("cvt.rn.satfinite.f16x2.f32 %0, %1, %2;" : "=r"(r) : "f"(hi), "f"(lo));
    return r;
}
// D = A(16x16,row) * B(16x8,col) + C, f16 inputs, f32 accum
__device__ __forceinline__ void mma16816(float* d, const uint32_t* a,
                                         uint32_t b0, uint32_t b1) {
    asm volatile(
        "mma.sync.aligned.m16n8k16.row.col.f32.f16.f16.f32 "
        "{%0,%1,%2,%3}, {%4,%5,%6,%7}, {%8,%9}, {%0,%1,%2,%3};"
        : "+f"(d[0]), "+f"(d[1]), "+f"(d[2]), "+f"(d[3])
        : "r"(a[0]), "r"(a[1]), "r"(a[2]), "r"(a[3]), "r"(b0), "r"(b1));
}

// ---------------------------------------------------------------------------
// Node 1: GEMM partials
// ---------------------------------------------------------------------------
__global__ __launch_bounds__(NTHR, 4)
void main_kernel(const float* __restrict__ z,
                 const float* __restrict__ emb,
                 const float* __restrict__ lsig,
                 const float* __restrict__ eps,
                 const float* __restrict__ temp)
{
    __shared__ __align__(16) float2 sZ[ISLICE];          // (L2E*u*zx, L2E*u*zy)
    __shared__ __align__(16) float  sA2[ISLICE];         // L2E*alpha*|z|^2
    __shared__ __align__(16) __half sGt[N_EMB][ISLICE];  // G^T: [emb][i]

    const int tid = threadIdx.x;
    const int wid = tid >> 5;
    const int lid = tid & 31;
    const int gid = lid >> 2;          // 0..7
    const int tig = lid & 3;           // 0..3
    const int mt  = blockIdx.x & 7;    // m-tile: m0 = mt*128
    const int ks  = blockIdx.x >> 3;   // K-slice: i0 = ks*128

    const float T   = temp[0];
    const float ls  = lsig[0];
    const float u   = __expf(-2.0f * ls);   // 1/sigma^2
    const float alpha = -0.5f * u;
    const float L2E = 1.4426950408889634f;

    // --- prologue 1: scaled z slice into smem ---
    if (tid < ISLICE) {
        float2 zz = reinterpret_cast<const float2*>(z)[ks * ISLICE + tid];
        sZ[tid]  = make_float2(L2E * u * zz.x, L2E * u * zz.y);
        sA2[tid] = L2E * alpha * (zz.x * zz.x + zz.y * zz.y);
    }
    __syncthreads();

    // --- prologue 2: G^T[16][128] fp16 in smem (8 values per thread) ---
    {
        const int k  = tid & 15;
        const int i8 = (tid >> 4) * 8;
        const float mx = (1.0f - T) * emb[2 * k];
        const float my = (1.0f - T) * emb[2 * k + 1];
        uint32_t* dst = (uint32_t*)&sGt[k][i8];
#pragma unroll
        for (int ii = 0; ii < 8; ii += 2) {
            float2 z0 = sZ[i8 + ii], z1 = sZ[i8 + ii + 1];
            float g0 = ex2f(sA2[i8 + ii]     + fmaf(z0.x, mx, z0.y * my));
            float g1 = ex2f(sA2[i8 + ii + 1] + fmaf(z1.x, mx, z1.y * my));
            dst[ii >> 1] = cvt_f16x2(g0, g1);
        }
    }

    // --- this thread's two m rows (fragment rows gid, gid+8) ---
    const int m0g = mt * 128 + wid * 16 + gid;
    const int m1g = m0g + 8;
    const float2 e0 = reinterpret_cast<const float2*>(eps)[m0g];
    const float2 e1 = reinterpret_cast<const float2*>(eps)[m1g];
    const float tex0 = T * e0.x, tey0 = T * e0.y;
    const float tex1 = T * e1.x, tey1 = T * e1.y;

    __syncthreads();

    float acc[8];
#pragma unroll
    for (int q = 0; q < 8; q++) acc[q] = 0.0f;

    // --- main loop: 8 k-steps of 16 i; A frags computed in registers ---
#pragma unroll
    for (int step = 0; step < 8; step++) {
        const int iA = step * 16 + tig * 2;   // i: iA, iA+1, iA+8, iA+9
        float4 zp0 = *reinterpret_cast<const float4*>(&sZ[iA]);
        float4 zp1 = *reinterpret_cast<const float4*>(&sZ[iA + 8]);

        float h00 = ex2f(fmaf(zp0.x, tex0, zp0.y * tey0));
        float h01 = ex2f(fmaf(zp0.z, tex0, zp0.w * tey0));
        float h02 = ex2f(fmaf(zp1.x, tex0, zp1.y * tey0));
        float h03 = ex2f(fmaf(zp1.z, tex0, zp1.w * tey0));
        float h10 = ex2f(fmaf(zp0.x, tex1, zp0.y * tey1));
        float h11 = ex2f(fmaf(zp0.z, tex1, zp0.w * tey1));
        float h12 = ex2f(fmaf(zp1.x, tex1, zp1.y * tey1));
        float h13 = ex2f(fmaf(zp1.z, tex1, zp1.w * tey1));

        uint32_t a[4];
        a[0] = cvt_f16x2(h00, h01);   // A[gid  ][iA..iA+1]
        a[1] = cvt_f16x2(h10, h11);   // A[gid+8][iA..iA+1]
        a[2] = cvt_f16x2(h02, h03);   // A[gid  ][iA+8..iA+9]
        a[3] = cvt_f16x2(h12, h13);   // A[gid+8][iA+8..iA+9]

        uint32_t b0 = *(const uint32_t*)&sGt[gid][iA];
        uint32_t b1 = *(const uint32_t*)&sGt[gid][iA + 8];
        uint32_t b2 = *(const uint32_t*)&sGt[gid + 8][iA];
        uint32_t b3 = *(const uint32_t*)&sGt[gid + 8][iA + 8];

        mma16816(acc,     a, b0, b1);   // n = 0..7   (emb k = gid)
        mma16816(acc + 4, a, b2, b3);   // n = 8..15  (emb k = gid+8)
    }

    // --- epilogue: red.v2 into g_Ct[m][k]; no fence needed (kernel edge) ---
    asm volatile("red.global.add.v2.f32 [%0], {%1, %2};"
                 :: "l"(&g_Ct[m0g * N_EMB + tig * 2]), "f"(acc[0]), "f"(acc[1])
                 : "memory");
    asm volatile("red.global.add.v2.f32 [%0], {%1, %2};"
                 :: "l"(&g_Ct[m1g * N_EMB + tig * 2]), "f"(acc[2]), "f"(acc[3])
                 : "memory");
    asm volatile("red.global.add.v2.f32 [%0], {%1, %2};"
                 :: "l"(&g_Ct[m0g * N_EMB + 8 + tig * 2]), "f"(acc[4]), "f"(acc[5])
                 : "memory");
    asm volatile("red.global.add.v2.f32 [%0], {%1, %2};"
                 :: "l"(&g_Ct[m1g * N_EMB + 8 + tig * 2]), "f"(acc[6]), "f"(acc[7])
                 : "memory");
}

// ---------------------------------------------------------------------------
// Node 2: tail — lg2-sum of C (+reset), closed-form Sum|e|^2, final loss
// ---------------------------------------------------------------------------
__global__ __launch_bounds__(TAILTHR, 1)
void tail_kernel(const float* __restrict__ emb,
                 const float* __restrict__ lsig,
                 const float* __restrict__ eps,
                 const float* __restrict__ temp,
                 float* __restrict__ out)
{
    __shared__ float4 sred[TAILTHR];
    const int tid = threadIdx.x;

    const float T   = temp[0];
    const float ls  = lsig[0];
    const float u   = __expf(-2.0f * ls);
    const float alpha = -0.5f * u;
    const float LN2 = 0.6931471805599453f;

    float lgsum = 0.0f;
#pragma unroll
    for (int q2 = 0; q2 < M_TOT / (4 * TAILTHR); q2++) {   // 8 iters
        int j4 = q2 * TAILTHR + tid;
        float4 cc = reinterpret_cast<float4*>(g_Ct)[j4];
        reinterpret_cast<float4*>(g_Ct)[j4] = make_float4(0.f, 0.f, 0.f, 0.f);
        lgsum += lg2f(cc.x) + lg2f(cc.y) + lg2f(cc.z) + lg2f(cc.w);
    }
    // closed-form Sum_j |e_j|^2:
    //   = 1024*Sum_k|mk|^2 + 2T*(Sum_k mk)·(Sum_m em) + 16*T^2*Sum_m|em|^2
    float sx = 0.f, sy = 0.f, ss = 0.f;
#pragma unroll
    for (int q2 = 0; q2 < M_EPS / TAILTHR; q2++) {         // 2 iters
        int mm = q2 * TAILTHR + tid;
        float2 e = reinterpret_cast<const float2*>(eps)[mm];
        sx += e.x; sy += e.y; ss += e.x * e.x + e.y * e.y;
    }
    sred[tid] = make_float4(lgsum, sx, sy, ss);
    __syncthreads();
#pragma unroll
    for (int s = TAILTHR / 2; s > 0; s >>= 1) {
        if (tid < s) {
            float4 a = sred[tid], b = sred[tid + s];
            sred[tid] = make_float4(a.x + b.x, a.y + b.y, a.z + b.z, a.w + b.w);
        }
        __syncthreads();
    }
    if (tid == 0) {
        float4 r = sred[0];
        float mkx = 0.f, mky = 0.f, mk2 = 0.f;
        for (int k = 0; k < N_EMB; k++) {
            float mxk = (1.0f - T) * emb[2 * k];
            float myk = (1.0f - T) * emb[2 * k + 1];
            mkx += mxk; mky += myk; mk2 += mxk * mxk + myk * myk;
        }
        float Se = (float)M_EPS * mk2
                 + 2.0f * T * (mkx * r.y + mky * r.z)
                 + (float)N_EMB * T * T * r.w;
        float sum_lse = alpha * Se + LN2 * r.x;
        out[0] = -sum_lse / (float)M_TOT + (2.0f * ls - 1.0f) + logf((float)N_Z);
    }
}

// ---------------------------------------------------------------------------
extern "C" void kernel_launch(void* const* d_in, const int* in_sizes, int n_in,
                              void* d_out, int out_size)
{
    const float* z    = (const float*)d_in[0];
    const float* emb  = (const float*)d_in[1];
    const float* lsig = (const float*)d_in[2];
    const float* eps  = (const float*)d_in[3];
    const float* temp = (const float*)d_in[4];
    float* out = (float*)d_out;

    main_kernel<<<GRID, NTHR>>>(z, emb, lsig, eps, temp);
    tail_kernel<<<1, TAILTHR>>>(emb, lsig, eps, temp, out);
}